// round 1
// baseline (speedup 1.0000x reference)
#include <cuda_runtime.h>
#include <math.h>

#define B_    64
#define L_    197
#define D_    192
#define H_    3
#define DH_   64
#define MM_   128
#define TM_   256           // 2M
#define NT_   (B_*L_)       // 12608
#define FF_   768
#define NCLS_ 1000
#define NP_   (B_*196)      // 12544

// ---------------- scratch (static device globals; no allocation) ----------------
__device__ float g_xc[NT_*D_];
__device__ float g_q [NT_*D_];
__device__ float g_k [NT_*D_];
__device__ float g_v [NT_*D_];
__device__ float g_Qp[NT_*H_*TM_];
__device__ float g_Kp[NT_*H_*TM_];
__device__ float g_KV[B_*H_*TM_*DH_];
__device__ float g_Ks[B_*H_*TM_];
__device__ float g_at[NT_*D_];
__device__ float g_tp[NT_*D_];
__device__ float g_h1[NT_*FF_];
__device__ float g_pl[B_*D_];
__device__ float g_im[NP_*768];

// ---------------- GEMM: C[N,Mo] = A[N,K] @ W[Mo,K]^T (+bias, +add, relu) --------
// 64x64 tile, BK=16, 256 threads, 4x4 register blocking. N must be multiple of 64,
// K multiple of 16. Mo arbitrary (col guards).
__global__ void sgemm_kernel(const float* __restrict__ A, const float* __restrict__ W,
                             const float* __restrict__ bias, const float* __restrict__ add,
                             float* __restrict__ C, int N, int K, int Mo, int relu)
{
    __shared__ __align__(16) float As[16][68];
    __shared__ __align__(16) float Bs[16][68];
    const int bm = blockIdx.y * 64;
    const int bn = blockIdx.x * 64;
    const int tid = threadIdx.x;
    const int tx = tid & 15, ty = tid >> 4;
    const int lc = tid & 15, lr = tid >> 4;

    float acc[4][4];
#pragma unroll
    for (int i = 0; i < 4; i++)
#pragma unroll
        for (int j = 0; j < 4; j++) acc[i][j] = 0.f;

    for (int k0 = 0; k0 < K; k0 += 16) {
#pragma unroll
        for (int i = 0; i < 4; i++) {
            int r = lr + i * 16;
            As[lc][r] = A[(size_t)(bm + r) * K + k0 + lc];
            int wr = bn + r;
            Bs[lc][r] = (wr < Mo) ? W[(size_t)wr * K + k0 + lc] : 0.f;
        }
        __syncthreads();
#pragma unroll
        for (int kk = 0; kk < 16; kk++) {
            float4 a4 = *reinterpret_cast<const float4*>(&As[kk][ty * 4]);
            float4 b4 = *reinterpret_cast<const float4*>(&Bs[kk][tx * 4]);
            float av[4] = {a4.x, a4.y, a4.z, a4.w};
            float bv[4] = {b4.x, b4.y, b4.z, b4.w};
#pragma unroll
            for (int i = 0; i < 4; i++)
#pragma unroll
                for (int j = 0; j < 4; j++) acc[i][j] += av[i] * bv[j];
        }
        __syncthreads();
    }
#pragma unroll
    for (int i = 0; i < 4; i++) {
        int row = bm + ty * 4 + i;
#pragma unroll
        for (int j = 0; j < 4; j++) {
            int col = bn + tx * 4 + j;
            if (col < Mo) {
                float v = acc[i][j] + bias[col];
                if (add)  v += add[(size_t)row * Mo + col];
                if (relu) v = fmaxf(v, 0.f);
                C[(size_t)row * Mo + col] = v;
            }
        }
    }
}

// ---------------- im2col for 16x16/stride16 conv ----------------
__global__ void im2col_kernel(const float* __restrict__ x, float* __restrict__ out)
{
    int o = blockIdx.x * 256 + threadIdx.x;
    if (o >= NP_ * 768) return;
    int kk = o % 768;
    int t  = o / 768;
    int b = t / 196, p = t % 196;
    int gh = p / 14, gw = p % 14;
    int c = kk / 256, r = kk % 256;
    int pp = r / 16, qq = r % 16;
    out[o] = x[((size_t)(b * 3 + c) * 224 + gh * 16 + pp) * 224 + gw * 16 + qq];
}

// ---------------- LayerNorm helpers (192 threads/block) ----------------
__device__ __forceinline__ void block_stats192(float x, float* sh, float& mu, float& rs)
{
    float s = x, ss = x * x;
#pragma unroll
    for (int o = 16; o; o >>= 1) {
        s  += __shfl_down_sync(0xffffffffu, s,  o);
        ss += __shfl_down_sync(0xffffffffu, ss, o);
    }
    int w = threadIdx.x >> 5;
    if ((threadIdx.x & 31) == 0) { sh[w] = s; sh[6 + w] = ss; }
    __syncthreads();
    if (threadIdx.x == 0) {
        float a = 0.f, b = 0.f;
        for (int i = 0; i < 6; i++) { a += sh[i]; b += sh[6 + i]; }
        float m = a * (1.f / 192.f);
        float v = b * (1.f / 192.f) - m * m;
        sh[0] = m; sh[1] = rsqrtf(v + 1e-5f);
    }
    __syncthreads();
    mu = sh[0]; rs = sh[1];
}

__global__ void ln_kernel(const float* __restrict__ X, const float* __restrict__ g,
                          const float* __restrict__ bb, float* __restrict__ Y)
{
    int row = blockIdx.x, tid = threadIdx.x;
    __shared__ float sh[12];
    float x = X[(size_t)row * D_ + tid];
    float mu, rs;
    block_stats192(x, sh, mu, rs);
    Y[(size_t)row * D_ + tid] = (x - mu) * rs * g[tid] + bb[tid];
}

__global__ void dln_kernel(const float* __restrict__ X,
                           const float* __restrict__ g1, const float* __restrict__ b1,
                           const float* __restrict__ g2, const float* __restrict__ b2,
                           float* __restrict__ Y)
{
    int row = blockIdx.x, tid = threadIdx.x;
    __shared__ float sh[12];
    float x = X[(size_t)row * D_ + tid];
    float mu, rs;
    block_stats192(x, sh, mu, rs);
    float y = (x - mu) * rs * g1[tid] + b1[tid];
    __syncthreads();
    block_stats192(y, sh, mu, rs);
    Y[(size_t)row * D_ + tid] = (y - mu) * rs * g2[tid] + b2[tid];
}

__global__ void ln_patch_kernel(const float* __restrict__ T, const float* __restrict__ g,
                                const float* __restrict__ bb, const float* __restrict__ pos,
                                float* __restrict__ XC)
{
    int row = blockIdx.x, tid = threadIdx.x;   // row in [0, NP_)
    __shared__ float sh[12];
    float x = T[(size_t)row * D_ + tid];
    float mu, rs;
    block_stats192(x, sh, mu, rs);
    int b = row / 196, p = row % 196;
    float v = (x - mu) * rs * g[tid] + bb[tid] + pos[(size_t)(1 + p) * D_ + tid];
    XC[((size_t)b * L_ + 1 + p) * D_ + tid] = v;
}

__global__ void cls_kernel(const float* __restrict__ cls, const float* __restrict__ pos,
                           float* __restrict__ XC)
{
    int b = blockIdx.x, tid = threadIdx.x;
    XC[(size_t)b * L_ * D_ + tid] = cls[tid] + pos[tid];
}

// ---------------- FAVOR+ feature map ----------------
// X: [NT, D] (head-major rows). Phi: [NT, H*2M]. omega: [64,128] (this layer).
__global__ void favor_kernel(const float* __restrict__ X, const float* __restrict__ om,
                             float* __restrict__ Phi)
{
    int t = blockIdx.x, h = blockIdx.y, tid = threadIdx.x;  // 128 threads
    __shared__ float xs[64];
    __shared__ float offs;
    if (tid < 64) xs[tid] = X[(size_t)t * D_ + h * DH_ + tid] * 0.35355339059327373f;
    __syncthreads();
    if (tid < 32) {
        float a = xs[tid], b = xs[tid + 32];
        float s = a * a + b * b;
#pragma unroll
        for (int o = 16; o; o >>= 1) s += __shfl_down_sync(0xffffffffu, s, o);
        if (tid == 0) offs = 0.5f * s;
    }
    __syncthreads();
    float u = 0.f;
#pragma unroll
    for (int d = 0; d < 64; d++) u += xs[d] * om[d * MM_ + tid];
    float off = offs;
    float e1 = expf(u - off)  * 0.0625f;
    float e2 = expf(-u - off) * 0.0625f;
    size_t base = (size_t)t * (H_ * TM_) + h * TM_;
    Phi[base + tid]       = e1;
    Phi[base + MM_ + tid] = e2;
}

// ---------------- KV = Kp^T @ V per (b,h), plus Ksum ----------------
__global__ void kv_kernel(const float* __restrict__ Kp, const float* __restrict__ V,
                          float* __restrict__ KV, float* __restrict__ Ks)
{
    int b = blockIdx.x, h = blockIdx.y, m = threadIdx.x;  // 256 threads
    __shared__ float vs[64];
    float acc[64];
#pragma unroll
    for (int d = 0; d < 64; d++) acc[d] = 0.f;
    float ks = 0.f;
    for (int l = 0; l < L_; l++) {
        int t = b * L_ + l;
        if (m < 64) vs[m] = V[(size_t)t * D_ + h * DH_ + m];
        __syncthreads();
        float kp = Kp[(size_t)t * (H_ * TM_) + h * TM_ + m];
        ks += kp;
#pragma unroll
        for (int d = 0; d < 64; d++) acc[d] += kp * vs[d];
        __syncthreads();
    }
    size_t base = ((size_t)(b * H_ + h) * TM_ + m) * DH_;
#pragma unroll
    for (int d = 0; d < 64; d++) KV[base + d] = acc[d];
    Ks[(size_t)(b * H_ + h) * TM_ + m] = ks;
}

// ---------------- attn = Z * (Qp @ KV) per token ----------------
__global__ void attn_kernel(const float* __restrict__ Qp, const float* __restrict__ KV,
                            const float* __restrict__ Ks, float* __restrict__ O)
{
    int t = blockIdx.x, tid = threadIdx.x;   // 192 threads
    int b = t / L_;
    int h = tid >> 6, d = tid & 63;
    __shared__ float qs[768];
    __shared__ float zp[192];
    __shared__ float zsh[3];
#pragma unroll
    for (int j = 0; j < 4; j++) qs[tid + j * 192] = Qp[(size_t)t * 768 + tid + j * 192];
    __syncthreads();
    int bh = b * H_ + h;
    const float* ksr = Ks + (size_t)bh * TM_;
    const float* qh  = qs + h * TM_;
    float p = 0.f;
#pragma unroll
    for (int j = 0; j < 4; j++) p += qh[d * 4 + j] * ksr[d * 4 + j];
    zp[tid] = p;
    __syncthreads();
    if (d == 0) {
        float s = 0.f;
        for (int i = 0; i < 64; i++) s += zp[h * 64 + i];
        zsh[h] = 1.f / (s + 1e-6f);
    }
    __syncthreads();
    const float* kvb = KV + (size_t)bh * TM_ * DH_;
    float acc = 0.f;
#pragma unroll 8
    for (int mm = 0; mm < TM_; mm++) acc += qh[mm] * kvb[mm * DH_ + d];
    O[(size_t)t * D_ + tid] = acc * zsh[h];
}

// ---------------- mean pool over sequence ----------------
__global__ void pool_kernel(const float* __restrict__ XC, float* __restrict__ P)
{
    int b = blockIdx.x, tid = threadIdx.x;
    float s = 0.f;
    for (int l = 0; l < L_; l++) s += XC[((size_t)b * L_ + l) * D_ + tid];
    P[(size_t)b * D_ + tid] = s * (1.f / 197.f);
}

// ---------------- launcher ----------------
extern "C" void kernel_launch(void* const* d_in, const int* in_sizes, int n_in,
                              void* d_out, int out_size)
{
    (void)in_sizes; (void)n_in; (void)out_size;
    const float* x    = (const float*)d_in[0];
    const float* pw   = (const float*)d_in[1];
    const float* pb   = (const float*)d_in[2];
    const float* peg  = (const float*)d_in[3];
    const float* peb  = (const float*)d_in[4];
    const float* cls  = (const float*)d_in[5];
    const float* pos  = (const float*)d_in[6];
    const float* Wq   = (const float*)d_in[7];
    const float* bq   = (const float*)d_in[8];
    const float* Wk   = (const float*)d_in[9];
    const float* bk   = (const float*)d_in[10];
    const float* Wv   = (const float*)d_in[11];
    const float* bv   = (const float*)d_in[12];
    const float* Wo   = (const float*)d_in[13];
    const float* bo   = (const float*)d_in[14];
    const float* l1g  = (const float*)d_in[15];
    const float* l1b  = (const float*)d_in[16];
    const float* l2g  = (const float*)d_in[17];
    const float* l2b  = (const float*)d_in[18];
    const float* lbg  = (const float*)d_in[19];
    const float* lbb  = (const float*)d_in[20];
    const float* W1   = (const float*)d_in[21];
    const float* b1   = (const float*)d_in[22];
    const float* W2   = (const float*)d_in[23];
    const float* b2   = (const float*)d_in[24];
    const float* om   = (const float*)d_in[25];
    const float* hw   = (const float*)d_in[26];
    const float* hb   = (const float*)d_in[27];
    float* out = (float*)d_out;

    float *xc, *q, *k, *v, *Qp, *Kp, *KV, *Ks, *at, *tp, *h1, *pl, *im;
    cudaGetSymbolAddress((void**)&xc, g_xc);
    cudaGetSymbolAddress((void**)&q,  g_q);
    cudaGetSymbolAddress((void**)&k,  g_k);
    cudaGetSymbolAddress((void**)&v,  g_v);
    cudaGetSymbolAddress((void**)&Qp, g_Qp);
    cudaGetSymbolAddress((void**)&Kp, g_Kp);
    cudaGetSymbolAddress((void**)&KV, g_KV);
    cudaGetSymbolAddress((void**)&Ks, g_Ks);
    cudaGetSymbolAddress((void**)&at, g_at);
    cudaGetSymbolAddress((void**)&tp, g_tp);
    cudaGetSymbolAddress((void**)&h1, g_h1);
    cudaGetSymbolAddress((void**)&pl, g_pl);
    cudaGetSymbolAddress((void**)&im, g_im);

    // ---- patch embedding: im2col + GEMM + LN + pos, cls token ----
    {
        int tot = NP_ * 768;
        im2col_kernel<<<(tot + 255) / 256, 256>>>(x, im);
        sgemm_kernel<<<dim3(3, NP_ / 64), 256>>>(im, pw, pb, nullptr, q, NP_, 768, D_, 0);
        ln_patch_kernel<<<NP_, 192>>>(q, peg, peb, pos, xc);
        cls_kernel<<<B_, 192>>>(cls, pos, xc);
    }

    const dim3 gD(3, NT_ / 64);     // Mo=192
    const dim3 gF(12, NT_ / 64);    // Mo=768

    for (int i = 0; i < 12; i++) {
        const float* om_i = om + (size_t)i * DH_ * MM_;
        sgemm_kernel<<<gD, 256>>>(xc, Wq + (size_t)i * D_ * D_, bq + i * D_, nullptr, q, NT_, D_, D_, 0);
        sgemm_kernel<<<gD, 256>>>(xc, Wk + (size_t)i * D_ * D_, bk + i * D_, nullptr, k, NT_, D_, D_, 0);
        sgemm_kernel<<<gD, 256>>>(xc, Wv + (size_t)i * D_ * D_, bv + i * D_, nullptr, v, NT_, D_, D_, 0);
        favor_kernel<<<dim3(NT_, H_), 128>>>(q, om_i, Qp);
        favor_kernel<<<dim3(NT_, H_), 128>>>(k, om_i, Kp);
        kv_kernel<<<dim3(B_, H_), 256>>>(Kp, v, KV, Ks);
        attn_kernel<<<NT_, 192>>>(Qp, KV, Ks, at);
        // xc_new_pre = xc + attn @ Wo^T + bo
        sgemm_kernel<<<gD, 256>>>(at, Wo + (size_t)i * D_ * D_, bo + i * D_, xc, tp, NT_, D_, D_, 0);
        ln_kernel<<<NT_, 192>>>(tp, l1g + i * D_, l1b + i * D_, xc);
        // MLP
        sgemm_kernel<<<gF, 256>>>(xc, W1 + (size_t)i * FF_ * D_, b1 + i * FF_, nullptr, h1, NT_, D_, FF_, 1);
        sgemm_kernel<<<gD, 256>>>(h1, W2 + (size_t)i * D_ * FF_, b2 + i * D_, xc, tp, NT_, FF_, D_, 0);
        dln_kernel<<<NT_, 192>>>(tp, l2g + i * D_, l2b + i * D_, lbg + i * D_, lbb + i * D_, xc);

        if (i == 3 || i == 7 || i == 11) {
            int j = (i == 3) ? 0 : (i == 7) ? 1 : 2;
            pool_kernel<<<B_, 192>>>(xc, pl);
            sgemm_kernel<<<dim3(16, 1), 256>>>(pl, hw + (size_t)j * NCLS_ * D_, hb + j * NCLS_,
                                               nullptr, out + (size_t)j * B_ * NCLS_, B_, D_, NCLS_, 0);
        }
    }
}